// round 4
// baseline (speedup 1.0000x reference)
#include <cuda_runtime.h>
#include <cstdint>

#define T_STEPS 512
#define BATCH   256
#define N1      512
#define N2      256
#define N3      64
#define N4      784

// Scratch (no allocations allowed)
__device__ int      g_ctr[8];                        // per-nchunk steal counters
__device__ int      g_cnt[T_STEPS * BATCH];          // spike count per (t,b)
__device__ uint4    g_idx4[T_STEPS * BATCH * 4];     // 64 byte-indices per (t,b), zero-padded (8 MB)
__device__ float    g_WT[N2 * N1];                   // W_lif^T : [i][n] (512 KB)
__device__ float    g_WliT[N1 * N2];                 // W_li^T  : [k][j] (512 KB)
__device__ float    g_S[BATCH * N1];                 // weighted spike sums

// ---------------------------------------------------------------------------
// Kernel 0: reset steal counters (graph-replayed every launch)
// ---------------------------------------------------------------------------
__global__ void init_kernel() {
    if (threadIdx.x < 8) g_ctr[threadIdx.x] = 0;
}

// ---------------------------------------------------------------------------
// Kernel 1: pack spikes into per-(t,b) byte index lists + counts.
// One warp per (t,b) row; 4 warps per block.
// ---------------------------------------------------------------------------
__global__ void __launch_bounds__(128) pack_kernel(const float* __restrict__ spk) {
    const int warp = threadIdx.x >> 5, lane = threadIdx.x & 31;
    const int tb = blockIdx.x * 4 + warp;
    const float* row = spk + (size_t)tb * N2;

    uint32_t mw[8];
    #pragma unroll
    for (int w = 0; w < 8; w++) {
        float v = row[w * 32 + lane];
        mw[w] = __ballot_sync(0xffffffffu, v > 0.5f);
    }

    // zero-fill the 64-byte index slot (padding = index 0)
    uint32_t* idx32 = reinterpret_cast<uint32_t*>(g_idx4) + (size_t)tb * 16;
    if (lane < 16) idx32[lane] = 0u;
    __syncwarp();

    uint32_t myw = 0;
    #pragma unroll
    for (int k = 0; k < 8; k++) myw = (lane == k) ? mw[k] : myw;
    int c = (lane < 8) ? __popc(myw) : 0;

    int off = c;
    #pragma unroll
    for (int d = 1; d < 8; d <<= 1) {
        int o = __shfl_up_sync(0xffffffffu, off, d);
        if (lane >= d) off += o;
    }
    const int excl  = off - c;
    const int total = __shfl_sync(0xffffffffu, off, 7);

    if (lane < 8) {
        uint32_t m = myw;
        int p = excl;
        uint8_t* dst = reinterpret_cast<uint8_t*>(g_idx4) + (size_t)tb * 64;
        while (m) {
            int i = __ffs(m) - 1;
            m &= m - 1;
            if (p < 64) dst[p] = (uint8_t)(lane * 32 + i);
            p++;
        }
    }
    if (lane == 0) g_cnt[tb] = min(total, 64);
}

// ---------------------------------------------------------------------------
// Kernel 2: generic 32x32 tiled transpose  dst[c][r] = src[r][c]
// grid = (cols/32, rows/32)
// ---------------------------------------------------------------------------
__global__ void transpose_kernel(const float* __restrict__ src, float* __restrict__ dst,
                                 int rows, int cols) {
    __shared__ float tile[32][33];
    int bx = blockIdx.x, by = blockIdx.y;
    int tx = threadIdx.x, ty = threadIdx.y;
    #pragma unroll
    for (int r = ty; r < 32; r += 8)
        tile[r][tx] = src[(size_t)(by * 32 + r) * cols + bx * 32 + tx];
    __syncthreads();
    #pragma unroll
    for (int r = ty; r < 32; r += 8)
        dst[(size_t)(bx * 32 + r) * rows + by * 32 + tx] = tile[tx][r];
}

// ---------------------------------------------------------------------------
// Kernel 3: fused sparse-current + LIF scan + weighted spike accumulation.
// Block pinned to one 64-neuron chunk (W slice in 64 KB smem); its 8 warps
// steal whole batches from a per-nchunk atomic counter (time-balanced).
// Warp = 1 batch x 64 neurons (float2/lane).
// ---------------------------------------------------------------------------
__global__ void __launch_bounds__(256) scan_kernel(const float* __restrict__ b_lif) {
    extern __shared__ float Ws[];                   // [256][64] floats
    const int nchunk = blockIdx.x & 7;
    const int tid  = threadIdx.x;
    const int lane = tid & 31;
    const int nbase = nchunk * 64;

    #pragma unroll 4
    for (int idx = tid; idx < N2 * 64; idx += 256) {
        int i = idx >> 6, nl = idx & 63;
        Ws[idx] = g_WT[i * N1 + nbase + nl];
    }
    __syncthreads();

    const float2* WsF2 = reinterpret_cast<const float2*>(Ws);
    const int n0 = nbase + lane * 2;
    const float2 bl = *reinterpret_cast<const float2*>(b_lif + n0);
    const float2 W0 = WsF2[lane];                   // row 0 (padding compensation)
    const uint32_t* idxU = reinterpret_cast<const uint32_t*>(g_idx4);

    const float inv_beta = 1.0f / 0.95f;
    const float wnorm    = 1.0f / 25.6f;
    float pT = 0.95f;                               // beta_li^T via 9 squarings
    #pragma unroll
    for (int k = 0; k < 9; k++) pT *= pT;

    for (;;) {
        int task;
        if (lane == 0) task = atomicAdd(&g_ctr[nchunk], 1);
        task = __shfl_sync(0xffffffffu, task, 0);
        if (task >= BATCH) break;
        const int b = task;

        float mx = 0.0f, my = 0.0f;
        float Sx = 0.0f, Sy = 0.0f;
        float p = pT;

        // prefetch t=0
        int  n_nx = g_cnt[b];
        uint4 a_nx = g_idx4[(size_t)b * 4 + 0];
        uint4 b_nx = g_idx4[(size_t)b * 4 + 1];

        for (int t = 0; t < T_STEPS; t++) {
            const int n = n_nx;
            const uint32_t w0 = a_nx.x, w1 = a_nx.y, w2 = a_nx.z, w3 = a_nx.w;
            const uint32_t w4 = b_nx.x, w5 = b_nx.y, w6 = b_nx.z, w7 = b_nx.w;

            if (t < T_STEPS - 1) {                   // prefetch t+1
                const size_t tbn = (size_t)(t + 1) * BATCH + b;
                n_nx = g_cnt[tbn];
                a_nx = g_idx4[tbn * 4 + 0];
                b_nx = g_idx4[tbn * 4 + 1];
            }

            float cx = bl.x, cy = bl.y;

            #define GROUP_FULL(WW)                                              \
            {                                                                   \
                float2 v0 = WsF2[(((WW)      ) & 255u) * 32 + lane];            \
                float2 v1 = WsF2[(((WW) >>  8) & 255u) * 32 + lane];            \
                float2 v2 = WsF2[(((WW) >> 16) & 255u) * 32 + lane];            \
                float2 v3 = WsF2[ ((WW) >> 24)         * 32 + lane];            \
                cx += (v0.x + v1.x) + (v2.x + v3.x);                            \
                cy += (v0.y + v1.y) + (v2.y + v3.y);                            \
            }
            // 5 unconditional groups (20 slots), then up to 3 conditional ones.
            GROUP_FULL(w0) GROUP_FULL(w1) GROUP_FULL(w2) GROUP_FULL(w3) GROUP_FULL(w4)

            const int nf = min(n, 32);
            const int G  = max(5, (nf + 3) >> 2);    // groups actually processed
            if (G > 5) {
                GROUP_FULL(w5)
                if (G > 6) {
                    GROUP_FULL(w6)
                    if (G > 7) GROUP_FULL(w7)
                }
            }
            #undef GROUP_FULL

            // pads all hit row 0 -> one compensation FMA
            {
                float padf = (float)(4 * G - nf);
                cx = fmaf(padf, -W0.x, cx);
                cy = fmaf(padf, -W0.y, cy);
            }

            if (n > 32) {                            // rare overflow (~6% of steps)
                for (int g = 8; g * 4 < n; g++) {
                    uint32_t ww = idxU[(size_t)(t * BATCH + b) * 16 + g];
                    int r2 = n - g * 4;
                    float2 u0 = WsF2[((ww      ) & 255u) * 32 + lane];
                    float2 u1 = WsF2[((ww >>  8) & 255u) * 32 + lane];
                    float2 u2 = WsF2[((ww >> 16) & 255u) * 32 + lane];
                    float2 u3 = WsF2[ (ww >> 24)         * 32 + lane];
                    if (r2 < 2) { u1.x = 0.f; u1.y = 0.f; }
                    if (r2 < 3) { u2.x = 0.f; u2.y = 0.f; }
                    if (r2 < 4) { u3.x = 0.f; u3.y = 0.f; }
                    cx += (u0.x + u1.x) + (u2.x + u3.x);
                    cy += (u0.y + u1.y) + (u2.y + u3.y);
                }
            }

            // LIF membrane (subtract reset from previous-step mem)
            float rx = (mx > 1.0f) ? 1.0f : 0.0f;
            float ry = (my > 1.0f) ? 1.0f : 0.0f;
            mx = 0.9f * mx + cx - rx;
            my = 0.9f * my + cy - ry;
            float wt = (1.0f - p) * wnorm;
            if (mx > 1.0f) Sx += wt;
            if (my > 1.0f) Sy += wt;
            p *= inv_beta;
        }
        *reinterpret_cast<float2*>(g_S + b * N1 + n0) = make_float2(Sx, Sy);
    }
}

// ---------------------------------------------------------------------------
// Kernel 4: fused tail — one block per batch row.
// x[j] thread-per-output with transposed (coalesced, L2-resident) W_li^T,
// then h = relu(x@W1^T+b1), y = h@W2^T+b2, layernorm.
// ---------------------------------------------------------------------------
__global__ void __launch_bounds__(256) tail_kernel(
    const float* __restrict__ b_li,
    const float* __restrict__ W1,  const float* __restrict__ b1,
    const float* __restrict__ W2,  const float* __restrict__ b2,
    const float* __restrict__ ln_g, const float* __restrict__ ln_b,
    float* __restrict__ out)
{
    __shared__ float sS[N1];
    __shared__ float sx[N2];
    __shared__ float sh[N3];
    __shared__ float sy[N4];
    __shared__ float sred[16];
    const int b = blockIdx.x, tid = threadIdx.x;
    const int warp = tid >> 5, lane = tid & 31;

    sS[tid]       = g_S[b * N1 + tid];
    sS[tid + 256] = g_S[b * N1 + 256 + tid];
    __syncthreads();

    float pw = 0.95f;
    #pragma unroll
    for (int k = 0; k < 9; k++) pw *= pw;
    const float SW = (512.0f - 19.0f * (1.0f - pw)) / 25.6f;

    // x[j], j = tid: stream W_li^T rows (coalesced across threads, L2-hot)
    {
        float acc = SW * b_li[tid];
        const float* wt = g_WliT + tid;
        #pragma unroll 8
        for (int k = 0; k < N1; k++)
            acc = fmaf(sS[k], wt[(size_t)k * N2], acc);
        sx[tid] = acc;
    }
    __syncthreads();

    // h[o] = relu(W1[o,:].x + b1[o]) — warp computes 8 outputs (float2 lanes)
    const float2* sx2 = reinterpret_cast<const float2*>(sx);
    #pragma unroll
    for (int oo = 0; oo < 8; oo++) {
        int o = warp * 8 + oo;
        const float2* wrow = reinterpret_cast<const float2*>(W1 + (size_t)o * N2);
        float acc = 0.0f;
        #pragma unroll
        for (int it = 0; it < 4; it++) {
            int k2 = it * 32 + lane;
            float2 wv = wrow[k2], xv = sx2[k2];
            acc += wv.x * xv.x + wv.y * xv.y;
        }
        #pragma unroll
        for (int d = 16; d > 0; d >>= 1) acc += __shfl_xor_sync(0xffffffffu, acc, d);
        if (lane == 0) sh[o] = fmaxf(acc + b1[o], 0.0f);
    }
    __syncthreads();

    // y[o] = W2[o,:].h + b2[o] — warp-per-output, float2/lane
    const float2* hh = reinterpret_cast<const float2*>(sh);
    float2 hv = hh[lane];
    for (int g = 0; g < 98; g++) {
        int o = warp + g * 8;
        const float2* w2 = reinterpret_cast<const float2*>(W2 + (size_t)o * N3);
        float2 wv = w2[lane];
        float acc = wv.x * hv.x + wv.y * hv.y;
        #pragma unroll
        for (int d = 16; d > 0; d >>= 1) acc += __shfl_xor_sync(0xffffffffu, acc, d);
        if (lane == 0) sy[o] = acc + b2[o];
    }
    __syncthreads();

    // layernorm over 784
    float s = 0.0f;
    for (int k = tid; k < N4; k += 256) s += sy[k];
    #pragma unroll
    for (int o = 16; o > 0; o >>= 1) s += __shfl_xor_sync(0xffffffffu, s, o);
    if (lane == 0) sred[warp] = s;
    __syncthreads();
    if (tid < 32) {
        float v = (tid < 8) ? sred[tid] : 0.0f;
        #pragma unroll
        for (int o = 4; o > 0; o >>= 1) v += __shfl_xor_sync(0xffffffffu, v, o);
        if (tid == 0) sred[0] = v;
    }
    __syncthreads();
    const float mu = sred[0] / (float)N4;
    __syncthreads();

    float s2 = 0.0f;
    for (int k = tid; k < N4; k += 256) { float d = sy[k] - mu; s2 += d * d; }
    #pragma unroll
    for (int o = 16; o > 0; o >>= 1) s2 += __shfl_xor_sync(0xffffffffu, s2, o);
    if (lane == 0) sred[warp] = s2;
    __syncthreads();
    if (tid < 32) {
        float v = (tid < 8) ? sred[tid] : 0.0f;
        #pragma unroll
        for (int o = 4; o > 0; o >>= 1) v += __shfl_xor_sync(0xffffffffu, v, o);
        if (tid == 0) sred[0] = v;
    }
    __syncthreads();
    const float var  = sred[0] / (float)N4;
    const float rstd = rsqrtf(var + 1e-5f);

    for (int k = tid; k < N4; k += 256)
        out[(size_t)b * N4 + k] = (sy[k] - mu) * rstd * ln_g[k] + ln_b[k];
}

// ---------------------------------------------------------------------------
extern "C" void kernel_launch(void* const* d_in, const int* in_sizes, int n_in,
                              void* d_out, int out_size) {
    const float* spk   = (const float*)d_in[0];
    const float* W_lif = (const float*)d_in[1];
    const float* b_lif = (const float*)d_in[2];
    const float* W_li  = (const float*)d_in[3];
    const float* b_li  = (const float*)d_in[4];
    const float* W1    = (const float*)d_in[5];
    const float* b1    = (const float*)d_in[6];
    const float* W2    = (const float*)d_in[7];
    const float* b2    = (const float*)d_in[8];
    const float* ln_g  = (const float*)d_in[9];
    const float* ln_b  = (const float*)d_in[10];
    float* out = (float*)d_out;

    cudaFuncSetAttribute(scan_kernel, cudaFuncAttributeMaxDynamicSharedMemorySize, 65536);

    float* d_WT;   cudaGetSymbolAddress((void**)&d_WT,   g_WT);
    float* d_WliT; cudaGetSymbolAddress((void**)&d_WliT, g_WliT);

    init_kernel<<<1, 32>>>();
    pack_kernel<<<T_STEPS * BATCH / 4, 128>>>(spk);
    transpose_kernel<<<dim3(8, 16),  dim3(32, 8)>>>(W_lif, d_WT,   N1, N2);  // 512x256 -> 256x512
    transpose_kernel<<<dim3(16, 8),  dim3(32, 8)>>>(W_li,  d_WliT, N2, N1);  // 256x512 -> 512x256
    scan_kernel<<<152, 256, 65536>>>(b_lif);
    tail_kernel<<<BATCH, 256>>>(b_li, W1, b1, W2, b2, ln_g, ln_b, out);
}

// round 5
// speedup vs baseline: 1.0630x; 1.0630x over previous
#include <cuda_runtime.h>
#include <cstdint>

#define T_STEPS 512
#define BATCH   256
#define N1      512
#define N2      256
#define N3      64
#define N4      784

// Scratch (no allocations allowed)
__device__ int      g_cnt[T_STEPS * BATCH];          // spike count per (t,b)
__device__ uint4    g_idx4[T_STEPS * BATCH * 4];     // 64 byte-indices per (t,b), zero-padded (8 MB)
__device__ float    g_WT[N2 * N1];                   // W_lif^T : [i][n] (512 KB)
__device__ float    g_WliT[N1 * N2];                 // W_li^T  : [k][j] (512 KB)
__device__ float    g_S[BATCH * N1];                 // weighted spike sums

// ---------------------------------------------------------------------------
// Kernel 1: pack spikes into per-(t,b) byte index lists + counts.
// One warp per (t,b) row; 4 warps per block.
// ---------------------------------------------------------------------------
__global__ void __launch_bounds__(128) pack_kernel(const float* __restrict__ spk) {
    const int warp = threadIdx.x >> 5, lane = threadIdx.x & 31;
    const int tb = blockIdx.x * 4 + warp;
    const float* row = spk + (size_t)tb * N2;

    uint32_t mw[8];
    #pragma unroll
    for (int w = 0; w < 8; w++) {
        float v = row[w * 32 + lane];
        mw[w] = __ballot_sync(0xffffffffu, v > 0.5f);
    }

    // zero-fill the 64-byte index slot (padding = index 0)
    uint32_t* idx32 = reinterpret_cast<uint32_t*>(g_idx4) + (size_t)tb * 16;
    if (lane < 16) idx32[lane] = 0u;
    __syncwarp();

    uint32_t myw = 0;
    #pragma unroll
    for (int k = 0; k < 8; k++) myw = (lane == k) ? mw[k] : myw;
    int c = (lane < 8) ? __popc(myw) : 0;

    int off = c;
    #pragma unroll
    for (int d = 1; d < 8; d <<= 1) {
        int o = __shfl_up_sync(0xffffffffu, off, d);
        if (lane >= d) off += o;
    }
    const int excl  = off - c;
    const int total = __shfl_sync(0xffffffffu, off, 7);

    if (lane < 8) {
        uint32_t m = myw;
        int p = excl;
        uint8_t* dst = reinterpret_cast<uint8_t*>(g_idx4) + (size_t)tb * 64;
        while (m) {
            int i = __ffs(m) - 1;
            m &= m - 1;
            if (p < 64) dst[p] = (uint8_t)(lane * 32 + i);
            p++;
        }
    }
    if (lane == 0) g_cnt[tb] = min(total, 64);
}

// ---------------------------------------------------------------------------
// Kernel 2: generic 32x32 tiled transpose  dst[c][r] = src[r][c]
// ---------------------------------------------------------------------------
__global__ void transpose_kernel(const float* __restrict__ src, float* __restrict__ dst,
                                 int rows, int cols) {
    __shared__ float tile[32][33];
    int bx = blockIdx.x, by = blockIdx.y;
    int tx = threadIdx.x, ty = threadIdx.y;
    #pragma unroll
    for (int r = ty; r < 32; r += 8)
        tile[r][tx] = src[(size_t)(by * 32 + r) * cols + bx * 32 + tx];
    __syncthreads();
    #pragma unroll
    for (int r = ty; r < 32; r += 8)
        dst[(size_t)(bx * 32 + r) * rows + by * 32 + tx] = tile[tx][r];
}

// ---------------------------------------------------------------------------
// Kernel 3: fused sparse-current + LIF scan + weighted spike accumulation.
// 32-neuron chunks (32 KB W slice in smem) -> high occupancy (26+ warps/SM).
// Block = 32 neurons x 8 batches (256 thr). Grid = 16 nchunks x 32 bchunks.
// Warp = 1 batch x 32 neurons (1 float/lane). Fixed 7 unconditional groups.
// ---------------------------------------------------------------------------
__global__ void __launch_bounds__(256, 4) scan_kernel(const float* __restrict__ b_lif) {
    extern __shared__ float Ws[];                   // [256][32] floats = 32 KB
    const int nchunk = blockIdx.x & 15;
    const int bchunk = blockIdx.x >> 4;
    const int tid  = threadIdx.x;
    const int warp = tid >> 5, lane = tid & 31;
    const int b     = bchunk * 8 + warp;
    const int nbase = nchunk * 32;

    // Ws[i*32 + nl] = W_lif^T[i][nbase+nl]; float4 loads, fully coalesced
    {
        float4* Ws4 = reinterpret_cast<float4*>(Ws);
        #pragma unroll 4
        for (int idx = tid; idx < N2 * 8; idx += 256) {
            int i = idx >> 3, nl4 = idx & 7;
            Ws4[idx] = reinterpret_cast<const float4*>(g_WT + (size_t)i * N1 + nbase)[nl4];
        }
    }
    __syncthreads();

    const int n0 = nbase + lane;
    const float bl = b_lif[n0];
    const float W0 = Ws[lane];                      // row 0 (padding compensation)
    const uint32_t* idxU = reinterpret_cast<const uint32_t*>(g_idx4);

    float mem = 0.0f;
    float S   = 0.0f;

    float p = 0.95f;                                // beta_li^T via 9 squarings
    #pragma unroll
    for (int k = 0; k < 9; k++) p *= p;
    const float inv_beta = 1.0f / 0.95f;
    const float wnorm    = 1.0f / 25.6f;

    // prefetch t=0
    int  n_nx = g_cnt[b];
    uint4 a_nx = g_idx4[(size_t)b * 4 + 0];
    uint4 b_nx = g_idx4[(size_t)b * 4 + 1];

    for (int t = 0; t < T_STEPS; t++) {
        const int n = n_nx;
        const uint32_t w0 = a_nx.x, w1 = a_nx.y, w2 = a_nx.z, w3 = a_nx.w;
        const uint32_t w4 = b_nx.x, w5 = b_nx.y, w6 = b_nx.z, w7 = b_nx.w;

        if (t < T_STEPS - 1) {                       // prefetch t+1
            const size_t tbn = (size_t)(t + 1) * BATCH + b;
            n_nx = g_cnt[tbn];
            a_nx = g_idx4[tbn * 4 + 0];
            b_nx = g_idx4[tbn * 4 + 1];
        }

        float c = bl;

        // 7 unconditional groups (28 slots), zero-index padded
        #define GROUP_FULL(WW)                                       \
        {                                                            \
            float v0 = Ws[(((WW)      ) & 255u) * 32 + lane];        \
            float v1 = Ws[(((WW) >>  8) & 255u) * 32 + lane];        \
            float v2 = Ws[(((WW) >> 16) & 255u) * 32 + lane];        \
            float v3 = Ws[ ((WW) >> 24)         * 32 + lane];        \
            c += (v0 + v1) + (v2 + v3);                              \
        }
        GROUP_FULL(w0) GROUP_FULL(w1) GROUP_FULL(w2) GROUP_FULL(w3)
        GROUP_FULL(w4) GROUP_FULL(w5) GROUP_FULL(w6)
        #undef GROUP_FULL

        // compensate padding (pads hit row 0)
        c = fmaf((float)(28 - min(n, 28)), -W0, c);

        if (n > 28) {                                 // group 7 (value-zeroed remainder)
            int rem = n - 28;
            float v0 = Ws[((w7      ) & 255u) * 32 + lane];
            float v1 = Ws[((w7 >>  8) & 255u) * 32 + lane];
            float v2 = Ws[((w7 >> 16) & 255u) * 32 + lane];
            float v3 = Ws[ (w7 >> 24)         * 32 + lane];
            if (rem < 2) v1 = 0.f;
            if (rem < 3) v2 = 0.f;
            if (rem < 4) v3 = 0.f;
            c += (v0 + v1) + (v2 + v3);

            // rare overflow: n > 32 (~6% of steps)
            for (int g = 8; g * 4 < n; g++) {
                uint32_t ww = idxU[(size_t)(t * BATCH + b) * 16 + g];
                int r2 = n - g * 4;
                float u0 = Ws[((ww      ) & 255u) * 32 + lane];
                float u1 = Ws[((ww >>  8) & 255u) * 32 + lane];
                float u2 = Ws[((ww >> 16) & 255u) * 32 + lane];
                float u3 = Ws[ (ww >> 24)         * 32 + lane];
                if (r2 < 2) u1 = 0.f;
                if (r2 < 3) u2 = 0.f;
                if (r2 < 4) u3 = 0.f;
                c += (u0 + u1) + (u2 + u3);
            }
        }

        // LIF membrane (subtract reset from previous-step mem)
        float r = (mem > 1.0f) ? 1.0f : 0.0f;
        mem = 0.9f * mem + c - r;
        float wt = (1.0f - p) * wnorm;
        if (mem > 1.0f) S += wt;
        p *= inv_beta;
    }
    g_S[b * N1 + n0] = S;                            // coalesced (n0 contiguous)
}

// ---------------------------------------------------------------------------
// Kernel 4: fused tail — one block per batch row.
// x[j] thread-per-output with transposed (coalesced, L2-resident) W_li^T,
// then h = relu(x@W1^T+b1), y = h@W2^T+b2, layernorm.
// ---------------------------------------------------------------------------
__global__ void __launch_bounds__(256) tail_kernel(
    const float* __restrict__ b_li,
    const float* __restrict__ W1,  const float* __restrict__ b1,
    const float* __restrict__ W2,  const float* __restrict__ b2,
    const float* __restrict__ ln_g, const float* __restrict__ ln_b,
    float* __restrict__ out)
{
    __shared__ float sS[N1];
    __shared__ float sx[N2];
    __shared__ float sh[N3];
    __shared__ float sy[N4];
    __shared__ float sred[16];
    const int b = blockIdx.x, tid = threadIdx.x;
    const int warp = tid >> 5, lane = tid & 31;

    sS[tid]       = g_S[b * N1 + tid];
    sS[tid + 256] = g_S[b * N1 + 256 + tid];
    __syncthreads();

    float pw = 0.95f;
    #pragma unroll
    for (int k = 0; k < 9; k++) pw *= pw;
    const float SW = (512.0f - 19.0f * (1.0f - pw)) / 25.6f;

    // x[j], j = tid: stream W_li^T rows (coalesced across threads, L2-hot),
    // dual accumulators to halve the FMA dependency chain
    {
        float acc0 = SW * b_li[tid], acc1 = 0.0f;
        const float* wt = g_WliT + tid;
        #pragma unroll 8
        for (int k = 0; k < N1; k += 2) {
            acc0 = fmaf(sS[k],     wt[(size_t)k       * N2], acc0);
            acc1 = fmaf(sS[k + 1], wt[(size_t)(k + 1) * N2], acc1);
        }
        sx[tid] = acc0 + acc1;
    }
    __syncthreads();

    // h[o] = relu(W1[o,:].x + b1[o]) — warp computes 8 outputs (float2 lanes)
    const float2* sx2 = reinterpret_cast<const float2*>(sx);
    #pragma unroll
    for (int oo = 0; oo < 8; oo++) {
        int o = warp * 8 + oo;
        const float2* wrow = reinterpret_cast<const float2*>(W1 + (size_t)o * N2);
        float acc = 0.0f;
        #pragma unroll
        for (int it = 0; it < 4; it++) {
            int k2 = it * 32 + lane;
            float2 wv = wrow[k2], xv = sx2[k2];
            acc += wv.x * xv.x + wv.y * xv.y;
        }
        #pragma unroll
        for (int d = 16; d > 0; d >>= 1) acc += __shfl_xor_sync(0xffffffffu, acc, d);
        if (lane == 0) sh[o] = fmaxf(acc + b1[o], 0.0f);
    }
    __syncthreads();

    // y[o] = W2[o,:].h + b2[o] — warp-per-output, float2/lane
    const float2* hh = reinterpret_cast<const float2*>(sh);
    float2 hv = hh[lane];
    for (int g = 0; g < 98; g++) {
        int o = warp + g * 8;
        const float2* w2 = reinterpret_cast<const float2*>(W2 + (size_t)o * N3);
        float2 wv = w2[lane];
        float acc = wv.x * hv.x + wv.y * hv.y;
        #pragma unroll
        for (int d = 16; d > 0; d >>= 1) acc += __shfl_xor_sync(0xffffffffu, acc, d);
        if (lane == 0) sy[o] = acc + b2[o];
    }
    __syncthreads();

    // layernorm over 784
    float s = 0.0f;
    for (int k = tid; k < N4; k += 256) s += sy[k];
    #pragma unroll
    for (int o = 16; o > 0; o >>= 1) s += __shfl_xor_sync(0xffffffffu, s, o);
    if (lane == 0) sred[warp] = s;
    __syncthreads();
    if (tid < 32) {
        float v = (tid < 8) ? sred[tid] : 0.0f;
        #pragma unroll
        for (int o = 4; o > 0; o >>= 1) v += __shfl_xor_sync(0xffffffffu, v, o);
        if (tid == 0) sred[0] = v;
    }
    __syncthreads();
    const float mu = sred[0] / (float)N4;
    __syncthreads();

    float s2 = 0.0f;
    for (int k = tid; k < N4; k += 256) { float d = sy[k] - mu; s2 += d * d; }
    #pragma unroll
    for (int o = 16; o > 0; o >>= 1) s2 += __shfl_xor_sync(0xffffffffu, s2, o);
    if (lane == 0) sred[warp] = s2;
    __syncthreads();
    if (tid < 32) {
        float v = (tid < 8) ? sred[tid] : 0.0f;
        #pragma unroll
        for (int o = 4; o > 0; o >>= 1) v += __shfl_xor_sync(0xffffffffu, v, o);
        if (tid == 0) sred[0] = v;
    }
    __syncthreads();
    const float var  = sred[0] / (float)N4;
    const float rstd = rsqrtf(var + 1e-5f);

    for (int k = tid; k < N4; k += 256)
        out[(size_t)b * N4 + k] = (sy[k] - mu) * rstd * ln_g[k] + ln_b[k];
}

// ---------------------------------------------------------------------------
extern "C" void kernel_launch(void* const* d_in, const int* in_sizes, int n_in,
                              void* d_out, int out_size) {
    const float* spk   = (const float*)d_in[0];
    const float* W_lif = (const float*)d_in[1];
    const float* b_lif = (const float*)d_in[2];
    const float* W_li  = (const float*)d_in[3];
    const float* b_li  = (const float*)d_in[4];
    const float* W1    = (const float*)d_in[5];
    const float* b1    = (const float*)d_in[6];
    const float* W2    = (const float*)d_in[7];
    const float* b2    = (const float*)d_in[8];
    const float* ln_g  = (const float*)d_in[9];
    const float* ln_b  = (const float*)d_in[10];
    float* out = (float*)d_out;

    cudaFuncSetAttribute(scan_kernel, cudaFuncAttributeMaxDynamicSharedMemorySize, 32768);

    float* d_WT;   cudaGetSymbolAddress((void**)&d_WT,   g_WT);
    float* d_WliT; cudaGetSymbolAddress((void**)&d_WliT, g_WliT);

    pack_kernel<<<T_STEPS * BATCH / 4, 128>>>(spk);
    transpose_kernel<<<dim3(8, 16),  dim3(32, 8)>>>(W_lif, d_WT,   N1, N2);  // 512x256 -> 256x512
    transpose_kernel<<<dim3(16, 8),  dim3(32, 8)>>>(W_li,  d_WliT, N2, N1);  // 256x512 -> 512x256
    scan_kernel<<<512, 256, 32768>>>(b_lif);
    tail_kernel<<<BATCH, 256>>>(b_li, W1, b1, W2, b2, ln_g, ln_b, out);
}

// round 6
// speedup vs baseline: 1.5668x; 1.4740x over previous
#include <cuda_runtime.h>
#include <cstdint>

#define T_STEPS 512
#define BATCH   256
#define N1      512
#define N2      256
#define N3      64
#define N4      784

// Scratch (no allocations allowed)
__device__ int      g_ctr[4];                        // per-nchunk steal counters
__device__ int      g_cnt[T_STEPS * BATCH];          // spike count per (t,b)
__device__ uint4    g_idx4[T_STEPS * BATCH * 4];     // 64 byte-indices per (t,b), zero-padded (8 MB)
__device__ float    g_WT[N2 * N1];                   // W_lif^T : [i][n] (512 KB)
__device__ float    g_WliT[N1 * N2];                 // W_li^T  : [k][j] (512 KB)
__device__ float    g_S[BATCH * N1];                 // weighted spike sums

// ---------------------------------------------------------------------------
// Kernel 0: reset steal counters (graph-replayed every launch)
// ---------------------------------------------------------------------------
__global__ void init_kernel() {
    if (threadIdx.x < 4) g_ctr[threadIdx.x] = 0;
}

// ---------------------------------------------------------------------------
// Kernel 1: pack spikes into per-(t,b) byte index lists + counts.
// One warp per (t,b) row; 4 warps per block.
// ---------------------------------------------------------------------------
__global__ void __launch_bounds__(128) pack_kernel(const float* __restrict__ spk) {
    const int warp = threadIdx.x >> 5, lane = threadIdx.x & 31;
    const int tb = blockIdx.x * 4 + warp;
    const float* row = spk + (size_t)tb * N2;

    uint32_t mw[8];
    #pragma unroll
    for (int w = 0; w < 8; w++) {
        float v = row[w * 32 + lane];
        mw[w] = __ballot_sync(0xffffffffu, v > 0.5f);
    }

    // zero-fill the 64-byte index slot (padding = index 0)
    uint32_t* idx32 = reinterpret_cast<uint32_t*>(g_idx4) + (size_t)tb * 16;
    if (lane < 16) idx32[lane] = 0u;
    __syncwarp();

    uint32_t myw = 0;
    #pragma unroll
    for (int k = 0; k < 8; k++) myw = (lane == k) ? mw[k] : myw;
    int c = (lane < 8) ? __popc(myw) : 0;

    int off = c;
    #pragma unroll
    for (int d = 1; d < 8; d <<= 1) {
        int o = __shfl_up_sync(0xffffffffu, off, d);
        if (lane >= d) off += o;
    }
    const int excl  = off - c;
    const int total = __shfl_sync(0xffffffffu, off, 7);

    if (lane < 8) {
        uint32_t m = myw;
        int p = excl;
        uint8_t* dst = reinterpret_cast<uint8_t*>(g_idx4) + (size_t)tb * 64;
        while (m) {
            int i = __ffs(m) - 1;
            m &= m - 1;
            if (p < 64) dst[p] = (uint8_t)(lane * 32 + i);
            p++;
        }
    }
    if (lane == 0) g_cnt[tb] = min(total, 64);
}

// ---------------------------------------------------------------------------
// Kernel 2: generic 32x32 tiled transpose  dst[c][r] = src[r][c]
// ---------------------------------------------------------------------------
__global__ void transpose_kernel(const float* __restrict__ src, float* __restrict__ dst,
                                 int rows, int cols) {
    __shared__ float tile[32][33];
    int bx = blockIdx.x, by = blockIdx.y;
    int tx = threadIdx.x, ty = threadIdx.y;
    #pragma unroll
    for (int r = ty; r < 32; r += 8)
        tile[r][tx] = src[(size_t)(by * 32 + r) * cols + bx * 32 + tx];
    __syncthreads();
    #pragma unroll
    for (int r = ty; r < 32; r += 8)
        dst[(size_t)(bx * 32 + r) * rows + by * 32 + tx] = tile[tx][r];
}

// ---------------------------------------------------------------------------
// Kernel 3: fused sparse-current + LIF scan + weighted spike accumulation.
// float4/lane: warp = 1 batch x 128 neurons; one LDS.128 + 4 FADD per slot.
// Block pinned to one 128-neuron chunk, W slice = 256x128 fp32 = 128 KB smem.
// Grid = 152 blocks (4 nchunks x 38); warps steal batches per nchunk counter.
// ---------------------------------------------------------------------------
__global__ void __launch_bounds__(256, 1) scan_kernel(const float* __restrict__ b_lif) {
    extern __shared__ float Ws[];                   // [256][128] floats = 128 KB
    const int nchunk = blockIdx.x & 3;
    const int tid  = threadIdx.x;
    const int lane = tid & 31;
    const int nbase = nchunk * 128;

    // Ws[i][nl] = W_lif^T[i][nbase+nl]; float4 coalesced loads
    {
        float4* Ws4 = reinterpret_cast<float4*>(Ws);
        #pragma unroll 4
        for (int idx = tid; idx < N2 * 32; idx += 256) {
            int i = idx >> 5, c4 = idx & 31;
            Ws4[idx] = reinterpret_cast<const float4*>(g_WT + (size_t)i * N1 + nbase)[c4];
        }
    }
    __syncthreads();

    const float4* W4 = reinterpret_cast<const float4*>(Ws);
    const int n0 = nbase + lane * 4;
    const float4 bl = *reinterpret_cast<const float4*>(b_lif + n0);
    const float4 W0 = W4[lane];                     // row 0 (padding compensation)
    const uint32_t* idxU = reinterpret_cast<const uint32_t*>(g_idx4);

    const float inv_beta = 1.0f / 0.95f;
    const float wnorm    = 1.0f / 25.6f;
    float pT = 0.95f;                               // beta_li^T via 9 squarings
    #pragma unroll
    for (int k = 0; k < 9; k++) pT *= pT;

    for (;;) {
        int b;
        if (lane == 0) b = atomicAdd(&g_ctr[nchunk], 1);
        b = __shfl_sync(0xffffffffu, b, 0);
        if (b >= BATCH) break;

        float4 mem = make_float4(0.f, 0.f, 0.f, 0.f);
        float4 S   = make_float4(0.f, 0.f, 0.f, 0.f);
        float p = pT;

        // prefetch t=0
        int  n_nx = g_cnt[b];
        uint4 a_nx = g_idx4[(size_t)b * 4 + 0];
        uint4 b_nx = g_idx4[(size_t)b * 4 + 1];

        for (int t = 0; t < T_STEPS; t++) {
            const int n = n_nx;
            const uint32_t w0 = a_nx.x, w1 = a_nx.y, w2 = a_nx.z, w3 = a_nx.w;
            const uint32_t w4 = b_nx.x, w5 = b_nx.y, w6 = b_nx.z, w7 = b_nx.w;

            if (t < T_STEPS - 1) {                   // prefetch t+1
                const size_t tbn = (size_t)(t + 1) * BATCH + b;
                n_nx = g_cnt[tbn];
                a_nx = g_idx4[tbn * 4 + 0];
                b_nx = g_idx4[tbn * 4 + 1];
            }

            float4 c = bl;

            #define GROUP_FULL(WW)                                        \
            {                                                             \
                float4 v0 = W4[(((WW)      ) & 255u) * 32 + lane];        \
                float4 v1 = W4[(((WW) >>  8) & 255u) * 32 + lane];        \
                float4 v2 = W4[(((WW) >> 16) & 255u) * 32 + lane];        \
                float4 v3 = W4[ ((WW) >> 24)         * 32 + lane];        \
                c.x += (v0.x + v1.x) + (v2.x + v3.x);                     \
                c.y += (v0.y + v1.y) + (v2.y + v3.y);                     \
                c.z += (v0.z + v1.z) + (v2.z + v3.z);                     \
                c.w += (v0.w + v1.w) + (v2.w + v3.w);                     \
            }
            // 5 unconditional groups, then warp-uniform conditional 6/7/8
            GROUP_FULL(w0) GROUP_FULL(w1) GROUP_FULL(w2) GROUP_FULL(w3) GROUP_FULL(w4)

            const int nf = min(n, 32);
            const int G  = max(5, (nf + 3) >> 2);
            if (G > 5) {
                GROUP_FULL(w5)
                if (G > 6) {
                    GROUP_FULL(w6)
                    if (G > 7) GROUP_FULL(w7)
                }
            }
            #undef GROUP_FULL

            // pads all hit row 0 -> compensation FMAs
            {
                float padf = (float)(4 * G - nf);
                c.x = fmaf(padf, -W0.x, c.x);
                c.y = fmaf(padf, -W0.y, c.y);
                c.z = fmaf(padf, -W0.z, c.z);
                c.w = fmaf(padf, -W0.w, c.w);
            }

            if (n > 32) {                            // rare overflow (~6% of steps)
                for (int g = 8; g * 4 < n; g++) {
                    uint32_t ww = idxU[(size_t)(t * BATCH + b) * 16 + g];
                    int r2 = n - g * 4;
                    float4 u0 = W4[((ww      ) & 255u) * 32 + lane];
                    float4 u1 = W4[((ww >>  8) & 255u) * 32 + lane];
                    float4 u2 = W4[((ww >> 16) & 255u) * 32 + lane];
                    float4 u3 = W4[ (ww >> 24)         * 32 + lane];
                    if (r2 < 2) { u1.x = u1.y = u1.z = u1.w = 0.f; }
                    if (r2 < 3) { u2.x = u2.y = u2.z = u2.w = 0.f; }
                    if (r2 < 4) { u3.x = u3.y = u3.z = u3.w = 0.f; }
                    c.x += (u0.x + u1.x) + (u2.x + u3.x);
                    c.y += (u0.y + u1.y) + (u2.y + u3.y);
                    c.z += (u0.z + u1.z) + (u2.z + u3.z);
                    c.w += (u0.w + u1.w) + (u2.w + u3.w);
                }
            }

            // LIF membrane (subtract reset from previous-step mem)
            float4 r;
            r.x = (mem.x > 1.0f) ? 1.0f : 0.0f;
            r.y = (mem.y > 1.0f) ? 1.0f : 0.0f;
            r.z = (mem.z > 1.0f) ? 1.0f : 0.0f;
            r.w = (mem.w > 1.0f) ? 1.0f : 0.0f;
            mem.x = 0.9f * mem.x + c.x - r.x;
            mem.y = 0.9f * mem.y + c.y - r.y;
            mem.z = 0.9f * mem.z + c.z - r.z;
            mem.w = 0.9f * mem.w + c.w - r.w;
            float wt = (1.0f - p) * wnorm;
            if (mem.x > 1.0f) S.x += wt;
            if (mem.y > 1.0f) S.y += wt;
            if (mem.z > 1.0f) S.z += wt;
            if (mem.w > 1.0f) S.w += wt;
            p *= inv_beta;
        }
        *reinterpret_cast<float4*>(g_S + b * N1 + n0) = S;
    }
}

// ---------------------------------------------------------------------------
// Kernel 4: fused tail — one block per batch row.
// x[j] thread-per-output with transposed (coalesced, L2-resident) W_li^T,
// then h = relu(x@W1^T+b1), y = h@W2^T+b2, layernorm.
// ---------------------------------------------------------------------------
__global__ void __launch_bounds__(256) tail_kernel(
    const float* __restrict__ b_li,
    const float* __restrict__ W1,  const float* __restrict__ b1,
    const float* __restrict__ W2,  const float* __restrict__ b2,
    const float* __restrict__ ln_g, const float* __restrict__ ln_b,
    float* __restrict__ out)
{
    __shared__ float sS[N1];
    __shared__ float sx[N2];
    __shared__ float sh[N3];
    __shared__ float sy[N4];
    __shared__ float sred[16];
    const int b = blockIdx.x, tid = threadIdx.x;
    const int warp = tid >> 5, lane = tid & 31;

    sS[tid]       = g_S[b * N1 + tid];
    sS[tid + 256] = g_S[b * N1 + 256 + tid];
    __syncthreads();

    float pw = 0.95f;
    #pragma unroll
    for (int k = 0; k < 9; k++) pw *= pw;
    const float SW = (512.0f - 19.0f * (1.0f - pw)) / 25.6f;

    // x[j], j = tid: stream W_li^T rows (coalesced across threads, L2-hot)
    {
        float acc0 = SW * b_li[tid], acc1 = 0.0f;
        const float* wt = g_WliT + tid;
        #pragma unroll 8
        for (int k = 0; k < N1; k += 2) {
            acc0 = fmaf(sS[k],     wt[(size_t)k       * N2], acc0);
            acc1 = fmaf(sS[k + 1], wt[(size_t)(k + 1) * N2], acc1);
        }
        sx[tid] = acc0 + acc1;
    }
    __syncthreads();

    // h[o] = relu(W1[o,:].x + b1[o]) — warp computes 8 outputs (float2 lanes)
    const float2* sx2 = reinterpret_cast<const float2*>(sx);
    #pragma unroll
    for (int oo = 0; oo < 8; oo++) {
        int o = warp * 8 + oo;
        const float2* wrow = reinterpret_cast<const float2*>(W1 + (size_t)o * N2);
        float acc = 0.0f;
        #pragma unroll
        for (int it = 0; it < 4; it++) {
            int k2 = it * 32 + lane;
            float2 wv = wrow[k2], xv = sx2[k2];
            acc += wv.x * xv.x + wv.y * xv.y;
        }
        #pragma unroll
        for (int d = 16; d > 0; d >>= 1) acc += __shfl_xor_sync(0xffffffffu, acc, d);
        if (lane == 0) sh[o] = fmaxf(acc + b1[o], 0.0f);
    }
    __syncthreads();

    // y[o] = W2[o,:].h + b2[o] — warp-per-output, float2/lane
    const float2* hh = reinterpret_cast<const float2*>(sh);
    float2 hv = hh[lane];
    for (int g = 0; g < 98; g++) {
        int o = warp + g * 8;
        const float2* w2 = reinterpret_cast<const float2*>(W2 + (size_t)o * N3);
        float2 wv = w2[lane];
        float acc = wv.x * hv.x + wv.y * hv.y;
        #pragma unroll
        for (int d = 16; d > 0; d >>= 1) acc += __shfl_xor_sync(0xffffffffu, acc, d);
        if (lane == 0) sy[o] = acc + b2[o];
    }
    __syncthreads();

    // layernorm over 784
    float s = 0.0f;
    for (int k = tid; k < N4; k += 256) s += sy[k];
    #pragma unroll
    for (int o = 16; o > 0; o >>= 1) s += __shfl_xor_sync(0xffffffffu, s, o);
    if (lane == 0) sred[warp] = s;
    __syncthreads();
    if (tid < 32) {
        float v = (tid < 8) ? sred[tid] : 0.0f;
        #pragma unroll
        for (int o = 4; o > 0; o >>= 1) v += __shfl_xor_sync(0xffffffffu, v, o);
        if (tid == 0) sred[0] = v;
    }
    __syncthreads();
    const float mu = sred[0] / (float)N4;
    __syncthreads();

    float s2 = 0.0f;
    for (int k = tid; k < N4; k += 256) { float d = sy[k] - mu; s2 += d * d; }
    #pragma unroll
    for (int o = 16; o > 0; o >>= 1) s2 += __shfl_xor_sync(0xffffffffu, s2, o);
    if (lane == 0) sred[warp] = s2;
    __syncthreads();
    if (tid < 32) {
        float v = (tid < 8) ? sred[tid] : 0.0f;
        #pragma unroll
        for (int o = 4; o > 0; o >>= 1) v += __shfl_xor_sync(0xffffffffu, v, o);
        if (tid == 0) sred[0] = v;
    }
    __syncthreads();
    const float var  = sred[0] / (float)N4;
    const float rstd = rsqrtf(var + 1e-5f);

    for (int k = tid; k < N4; k += 256)
        out[(size_t)b * N4 + k] = (sy[k] - mu) * rstd * ln_g[k] + ln_b[k];
}

// ---------------------------------------------------------------------------
extern "C" void kernel_launch(void* const* d_in, const int* in_sizes, int n_in,
                              void* d_out, int out_size) {
    const float* spk   = (const float*)d_in[0];
    const float* W_lif = (const float*)d_in[1];
    const float* b_lif = (const float*)d_in[2];
    const float* W_li  = (const float*)d_in[3];
    const float* b_li  = (const float*)d_in[4];
    const float* W1    = (const float*)d_in[5];
    const float* b1    = (const float*)d_in[6];
    const float* W2    = (const float*)d_in[7];
    const float* b2    = (const float*)d_in[8];
    const float* ln_g  = (const float*)d_in[9];
    const float* ln_b  = (const float*)d_in[10];
    float* out = (float*)d_out;

    cudaFuncSetAttribute(scan_kernel, cudaFuncAttributeMaxDynamicSharedMemorySize, 131072);

    float* d_WT;   cudaGetSymbolAddress((void**)&d_WT,   g_WT);
    float* d_WliT; cudaGetSymbolAddress((void**)&d_WliT, g_WliT);

    init_kernel<<<1, 32>>>();
    pack_kernel<<<T_STEPS * BATCH / 4, 128>>>(spk);
    transpose_kernel<<<dim3(8, 16),  dim3(32, 8)>>>(W_lif, d_WT,   N1, N2);  // 512x256 -> 256x512
    transpose_kernel<<<dim3(16, 8),  dim3(32, 8)>>>(W_li,  d_WliT, N2, N1);  // 256x512 -> 512x256
    scan_kernel<<<152, 256, 131072>>>(b_lif);
    tail_kernel<<<BATCH, 256>>>(b_li, W1, b1, W2, b2, ln_g, ln_b, out);
}